// round 7
// baseline (speedup 1.0000x reference)
#include <cuda_runtime.h>
#include <cuda_bf16.h>
#include <cstdint>

// NCutsLoss, fused single kernel.
//   acc(b,k,h,w)   = sum_{m,n} padded[b,k,h+m,w+n] * weight[b,0,h,w,m,n]
//   assocA[b,k]    = sum_{h,w} acc * seg
//   assocV[b,k]    = sum_{h,w} sum_weight * seg
//   out[b]         = 8.0 - sum_k assocA/assocV
// B=16, K=8, H=W=128, WIN=9, padded 136x136.
//
// R7: pad tile staged in smem as bf16 (exact bit-shift read-back),
//     weight staged via cp.async with a DOUBLE buffer (copy of chunk c+1
//     overlaps compute of chunk c — no per-chunk wait exposure).

#define BB   16
#define KK   8
#define HH   128
#define WW   128
#define WIN  9
#define WQ   (WIN * WIN)      // 81
#define PH   (HH + WIN - 1)   // 136
#define PW   (WW + WIN - 1)   // 136

#define TH   16               // h-rows per block
#define PROWS (TH + WIN - 1)  // 24 padded rows
#define CHUNKP_E 3272         // bf16 elems per k-plane (3264 + 8; word-stride ≡ 4 mod 32)

#define WCH  16               // w-chunk width (pixels)
#define NCH  (WW / WCH)       // 8 chunks
#define ROWF (WCH * WQ)       // 1296 weight floats per (row, chunk)
#define ROWF4 (ROWF / 4)      // 324 float4

#define PAD_BYTES  (KK * CHUNKP_E * 2)          // 52,352
#define WSLOT_FLOATS (TH * ROWF)                // 20,736 floats per buffer slot
#define WBUF_BYTES (2 * WSLOT_FLOATS * 4)       // 165,888
#define SMEM_BYTES (PAD_BYTES + WBUF_BYTES)     // 218,240

#define NTILES (HH / TH)      // 8
#define NBLOCKS (BB * NTILES) // 128

__device__ float    g_part[BB * NTILES * 16];
__device__ unsigned g_ctr = 0;

__device__ __forceinline__ void cpa16(uint32_t dst_smem, const void* src) {
    asm volatile("cp.async.ca.shared.global [%0], [%1], 16;\n"
                 :: "r"(dst_smem), "l"(src));
}
__device__ __forceinline__ void cpa_commit() {
    asm volatile("cp.async.commit_group;\n");
}
__device__ __forceinline__ void cpa_wait1() {
    asm volatile("cp.async.wait_group 1;\n");
}
__device__ __forceinline__ void cpa_wait0() {
    asm volatile("cp.async.wait_group 0;\n");
}
// bf16 -> f32, exact (bit shift)
__device__ __forceinline__ float lo16(uint32_t u) { return __uint_as_float(u << 16); }
__device__ __forceinline__ float hi16(uint32_t u) { return __uint_as_float(u & 0xFFFF0000u); }

__global__ __launch_bounds__(512, 1)
void ncuts_fused_kernel(const float* __restrict__ seg,
                        const float* __restrict__ pad,
                        const float* __restrict__ wgt,
                        const float* __restrict__ sw,
                        float* __restrict__ out)
{
    extern __shared__ char smem_raw[];
    __nv_bfloat16* padsm = reinterpret_cast<__nv_bfloat16*>(smem_raw);     // [k][3272] bf16
    float*         wbuf  = reinterpret_cast<float*>(smem_raw + PAD_BYTES); // [2][16 rows][1296] f32

    const int b    = blockIdx.y;
    const int h0   = blockIdx.x * TH;
    const int tid  = threadIdx.x;           // 0..511
    const int lane = tid & 31;
    const int ty   = tid >> 5;              // warp id = h-row
    const int k    = lane & 7;              // k-plane per thread
    const int wq   = lane >> 3;             // w-quad within chunk (0..3)

    // Weight row base for this warp's h-row; rows are 16B-aligned (41,472 B each).
    const float* wrowbase = wgt + (((size_t)b * HH + h0 + ty) * WW) * WQ;
    float* myrow0 = wbuf + ty * ROWF;
    float* myrow1 = wbuf + WSLOT_FLOATS + ty * ROWF;
    const uint32_t myrow_s[2] = {
        (uint32_t)__cvta_generic_to_shared(myrow0),
        (uint32_t)__cvta_generic_to_shared(myrow1)
    };

    // ---- Issue async copy of weight chunk 0 into buffer 0 ----
    #pragma unroll
    for (int j = 0; j < 11; ++j) {
        int idx = j * 32 + lane;
        if (idx < ROWF4)
            cpa16(myrow_s[0] + idx * 16, wrowbase + idx * 4);
    }
    cpa_commit();

    // ---- Fill padded-seg tile as bf16 (block-cooperative, coalesced) ----
    #pragma unroll
    for (int kk = 0; kk < KK; ++kk) {
        const float4* src = reinterpret_cast<const float4*>(
            pad + ((size_t)(b * KK + kk) * PH + h0) * PW);
        __nv_bfloat16* dstp = padsm + kk * CHUNKP_E;
        for (int i = tid; i < (PROWS * PW) / 4; i += 512) {
            float4 v = src[i];
            uint32_t p0, p1;
            asm("cvt.rn.bf16x2.f32 %0, %1, %2;" : "=r"(p0) : "f"(v.y), "f"(v.x));
            asm("cvt.rn.bf16x2.f32 %0, %1, %2;" : "=r"(p1) : "f"(v.w), "f"(v.z));
            *reinterpret_cast<uint2*>(dstp + i * 4) = make_uint2(p0, p1);
        }
    }
    __syncthreads();   // pad tile ready (only block barrier before reduction)

    float vA = 0.0f, vV = 0.0f;

    #pragma unroll 1
    for (int c = 0; c < NCH; ++c) {
        // Issue copy of chunk c+1 into the other buffer BEFORE computing c.
        if (c + 1 < NCH) {
            const float* src = wrowbase + (size_t)(c + 1) * ROWF;
            const uint32_t dst = myrow_s[(c + 1) & 1];
            #pragma unroll
            for (int j = 0; j < 11; ++j) {
                int idx = j * 32 + lane;
                if (idx < ROWF4)
                    cpa16(dst + idx * 16, src + idx * 4);
            }
            cpa_commit();
            cpa_wait1();   // chunk c's group complete; c+1 still in flight
        } else {
            cpa_wait0();   // last chunk: drain everything
        }
        __syncwarp();

        const float* myrow = (c & 1) ? myrow1 : myrow0;
        const int wloc = c * WCH + wq * 4;   // first of this thread's 4 pixels

        // seg / sum_weight for the fold (f32 LDG, hidden under FMAs)
        float4 segv = *reinterpret_cast<const float4*>(
            seg + (((size_t)(b * KK + k) * HH + h0 + ty) * WW + wloc));
        float4 swv  = *reinterpret_cast<const float4*>(
            sw  + (((size_t)b * HH + h0 + ty) * WW + wloc));

        const float* sq = myrow + (wq * 4) * WQ;            // 4 packed slices
        const __nv_bfloat16* prow0 = padsm + (size_t)k * CHUNKP_E + ty * PW + wloc;

        float acc[4] = {0.0f, 0.0f, 0.0f, 0.0f};
        float4 carry[4];
        #pragma unroll
        for (int m = 0; m < WIN; ++m) {
            const int off = m & 3;           // compile-time per unrolled m

            // pad window row: 12 bf16 = 3x LDS.64 (8B-aligned), exact cvt
            const uint2* rp = reinterpret_cast<const uint2*>(prow0 + m * PW);
            uint2 a0 = rp[0], a1 = rp[1], a2 = rp[2];
            float vals[12] = {
                lo16(a0.x), hi16(a0.x), lo16(a0.y), hi16(a0.y),
                lo16(a1.x), hi16(a1.x), lo16(a1.y), hi16(a1.y),
                lo16(a2.x), hi16(a2.x), lo16(a2.y), hi16(a2.y)
            };

            #pragma unroll
            for (int p = 0; p < 4; ++p) {
                const float* ps = sq + p * WQ;
                float4 a, bq, cc;
                if (m == 0 || m == 4) {
                    const int base = (m == 0) ? 0 : 36;
                    a  = *reinterpret_cast<const float4*>(ps + base);
                    bq = *reinterpret_cast<const float4*>(ps + base + 4);
                    cc = *reinterpret_cast<const float4*>(ps + base + 8);
                } else if (m == 8) {
                    a  = *reinterpret_cast<const float4*>(ps + 72);
                    bq = *reinterpret_cast<const float4*>(ps + 76);
                    cc = make_float4(ps[80], 0.0f, 0.0f, 0.0f);
                } else {
                    const int f = ((m <= 3) ? (2 * m + 1) : (2 * m + 2)) * 4;
                    a  = carry[p];
                    bq = *reinterpret_cast<const float4*>(ps + f);
                    cc = *reinterpret_cast<const float4*>(ps + f + 4);
                }
                float tp[12] = { a.x,  a.y,  a.z,  a.w,
                                 bq.x, bq.y, bq.z, bq.w,
                                 cc.x, cc.y, cc.z, cc.w };
                carry[p] = cc;
                #pragma unroll
                for (int n = 0; n < WIN; ++n)
                    acc[p] = fmaf(vals[n + p], tp[off + n], acc[p]);
            }
        }

        // ---- Fold with seg / sum_weight ----
        vA = fmaf(acc[0], segv.x, vA);  vA = fmaf(acc[1], segv.y, vA);
        vA = fmaf(acc[2], segv.z, vA);  vA = fmaf(acc[3], segv.w, vA);
        vV = fmaf(swv.x, segv.x, vV);   vV = fmaf(swv.y, segv.y, vV);
        vV = fmaf(swv.z, segv.z, vV);   vV = fmaf(swv.w, segv.w, vV);

        __syncwarp();   // all lanes done reading this buffer before it is reissued
    }

    // ---- Reduce over wq (lanes sharing k are 8 apart) ----
    vA += __shfl_xor_sync(0xFFFFFFFFu, vA, 8);
    vA += __shfl_xor_sync(0xFFFFFFFFu, vA, 16);
    vV += __shfl_xor_sync(0xFFFFFFFFu, vV, 8);
    vV += __shfl_xor_sync(0xFFFFFFFFu, vV, 16);

    __shared__ float sred[16][16];   // [warp=h][0..7 A_k, 8..15 V_k]
    if (lane < 8) {
        sred[ty][lane]     = vA;
        sred[ty][8 + lane] = vV;
    }
    __syncthreads();
    if (tid < 16) {
        float s = 0.0f;
        #pragma unroll
        for (int wrp = 0; wrp < 16; ++wrp)
            s += sred[wrp][tid];
        g_part[(b * NTILES + blockIdx.x) * 16 + tid] = s;
        __threadfence();             // publish partials
    }
    __syncthreads();

    // ---- Last-block finalize (deterministic fixed-order sums) ----
    __shared__ unsigned s_last;
    __shared__ float fin[BB * 16];
    if (tid == 0) {
        unsigned old = atomicAdd(&g_ctr, 1u);
        s_last = (old == NBLOCKS - 1) ? 1u : 0u;
    }
    __syncthreads();
    if (s_last) {
        __threadfence();
        if (tid < BB * 16) {
            const int bb = tid >> 4, slot = tid & 15;
            float s = 0.0f;
            #pragma unroll
            for (int ht = 0; ht < NTILES; ++ht)
                s += g_part[(bb * NTILES + ht) * 16 + slot];
            fin[tid] = s;
        }
        __syncthreads();
        if (tid < BB) {
            float assoc = 0.0f;
            #pragma unroll
            for (int kk = 0; kk < KK; ++kk)
                assoc += fin[tid * 16 + kk] / fin[tid * 16 + 8 + kk];
            out[tid] = 8.0f - assoc;
        }
        if (tid == 0) g_ctr = 0;     // reset for next graph replay
    }
}

extern "C" void kernel_launch(void* const* d_in, const int* in_sizes, int n_in,
                              void* d_out, int out_size)
{
    const float *seg = nullptr, *pad = nullptr, *wgt = nullptr, *sw = nullptr;
    for (int i = 0; i < n_in; ++i) {
        int sz = in_sizes[i];
        if      (sz == BB * KK * HH * WW)        seg = (const float*)d_in[i];
        else if (sz == BB * KK * PH * PW)        pad = (const float*)d_in[i];
        else if (sz == BB * HH * WW * WQ)        wgt = (const float*)d_in[i];
        else if (sz == BB * HH * WW)             sw  = (const float*)d_in[i];
    }
    float* out = (float*)d_out;

    cudaFuncSetAttribute(ncuts_fused_kernel,
                         cudaFuncAttributeMaxDynamicSharedMemorySize, SMEM_BYTES);

    dim3 grid(NTILES, BB);     // 128 blocks, one wave
    ncuts_fused_kernel<<<grid, 512, SMEM_BYTES>>>(seg, pad, wgt, sw, out);
}